// round 2
// baseline (speedup 1.0000x reference)
#include <cuda_runtime.h>
#include <cuda_bf16.h>
#include <cstdint>

// ---------------------------------------------------------------------------
// SigLIP loss on sm_100 (no tcgen05 on this toolchain -> mma.sync bf16 HMMA).
//   k0: fp32 -> bf16 convert of both feature matrices into __device__ scratch
//   k1: 128x128 tile bf16 GEMM (mma.sync.m16n8k16, 3-stage cp.async pipeline)
//       with softplus loss fused on the register accumulators
//   k2: deterministic reduce of per-CTA double partials -> scalar
// ---------------------------------------------------------------------------

#define NTOK 16384
#define DDIM 512

#define BM 128
#define BN 128
#define BK 64                       // bf16 elems; 128 bytes per row
#define NK (DDIM / BK)              // 8 k-stages
#define STAGES 3
#define A_BYTES (BM * 128)          // 16 KB
#define B_BYTES (BN * 128)          // 16 KB
#define STAGE_BYTES (A_BYTES + B_BYTES)
#define SMEM_TOTAL (STAGES * STAGE_BYTES + 2048)

#define GRID_X (NTOK / BN)          // 128
#define GRID_Y (NTOK / BM)          // 128
#define NPART (GRID_X * GRID_Y)     // 16384

__device__ __align__(16) __nv_bfloat16 g_Abf[(size_t)NTOK * DDIM];
__device__ __align__(16) __nv_bfloat16 g_Bbf[(size_t)NTOK * DDIM];
__device__ double g_partials[NPART];

// ---------------- helpers ----------------
__device__ __forceinline__ uint32_t smem_u32(const void* p) {
    uint32_t a;
    asm("{ .reg .u64 t; cvta.to.shared.u64 t, %1; cvt.u32.u64 %0, t; }"
        : "=r"(a) : "l"(p));
    return a;
}
__device__ __forceinline__ void cp_async16(uint32_t dst, const void* src) {
    asm volatile("cp.async.cg.shared.global [%0], [%1], 16;"
                 :: "r"(dst), "l"(src));
}
__device__ __forceinline__ void cp_commit() {
    asm volatile("cp.async.commit_group;" ::: "memory");
}
template <int N>
__device__ __forceinline__ void cp_wait() {
    asm volatile("cp.async.wait_group %0;" :: "n"(N) : "memory");
}
__device__ __forceinline__ void ldsm4(uint32_t* r, uint32_t a) {
    asm volatile("ldmatrix.sync.aligned.m8n8.x4.shared.b16 {%0,%1,%2,%3}, [%4];"
                 : "=r"(r[0]), "=r"(r[1]), "=r"(r[2]), "=r"(r[3]) : "r"(a));
}
__device__ __forceinline__ void mma16816(float* c, const uint32_t* a,
                                         const uint32_t* b) {
    asm volatile(
        "mma.sync.aligned.m16n8k16.row.col.f32.bf16.bf16.f32 "
        "{%0,%1,%2,%3}, {%4,%5,%6,%7}, {%8,%9}, {%0,%1,%2,%3};"
        : "+f"(c[0]), "+f"(c[1]), "+f"(c[2]), "+f"(c[3])
        : "r"(a[0]), "r"(a[1]), "r"(a[2]), "r"(a[3]), "r"(b[0]), "r"(b[1]));
}

// ---------------- k0: fp32 -> bf16 convert ----------------
__global__ void convert_kernel(const float* __restrict__ A,
                               const float* __restrict__ B) {
    const size_t n4 = (size_t)NTOK * DDIM / 4;
    size_t i = (size_t)blockIdx.x * blockDim.x + threadIdx.x;
    if (i < n4) {
        float4 v = reinterpret_cast<const float4*>(A)[i];
        __nv_bfloat162* o = reinterpret_cast<__nv_bfloat162*>(g_Abf);
        o[2 * i + 0] = __float22bfloat162_rn(make_float2(v.x, v.y));
        o[2 * i + 1] = __float22bfloat162_rn(make_float2(v.z, v.w));
    } else if (i < 2 * n4) {
        size_t j = i - n4;
        float4 v = reinterpret_cast<const float4*>(B)[j];
        __nv_bfloat162* o = reinterpret_cast<__nv_bfloat162*>(g_Bbf);
        o[2 * j + 0] = __float22bfloat162_rn(make_float2(v.x, v.y));
        o[2 * j + 1] = __float22bfloat162_rn(make_float2(v.z, v.w));
    }
}

// ---------------- k1: GEMM + fused loss ----------------
__global__ void __launch_bounds__(256, 2)
gemm_loss_kernel(const int* __restrict__ fl_lab, const int* __restrict__ sl_lab,
                 const float* __restrict__ scale_p,
                 const float* __restrict__ bias_p) {
    extern __shared__ char smem_raw[];
    uint32_t raw = smem_u32(smem_raw);
    uint32_t base = (raw + 127u) & ~127u;              // 128B align for swizzle
    char* base_p = smem_raw + (base - raw);

    int* sFl = reinterpret_cast<int*>(base_p + STAGES * STAGE_BYTES);
    int* sSl = sFl + BM;
    float* red = reinterpret_cast<float*>(sSl + BN);   // 8 floats

    const int tid = threadIdx.x;
    const int wid = tid >> 5;
    const int lane = tid & 31;
    const int wm = wid & 3;          // 4 warps along M (32 rows each)
    const int wn = wid >> 2;         // 2 warps along N (64 cols each)
    const int m0 = blockIdx.y * BM;
    const int n0 = blockIdx.x * BN;

    const char* gA = reinterpret_cast<const char*>(g_Abf);
    const char* gB = reinterpret_cast<const char*>(g_Bbf);

    // labels into smem
    if (tid < BM) sFl[tid] = fl_lab[m0 + tid];
    else if (tid < BM + BN) sSl[tid - BM] = sl_lab[n0 + tid - BM];

    // ---- staged loads: thread t covers chunk (r = t>>3 + 32*i, c = t&7) ----
    const int lr = tid >> 3;         // base row 0..31
    const int lc = tid & 7;          // 16B chunk 0..7
    auto load_stage = [&](int s) {
        const uint32_t ab = base + (s % STAGES) * STAGE_BYTES;
        const uint32_t bb = ab + A_BYTES;
        const size_t kof = (size_t)s * 128;            // bytes into the K dim
        #pragma unroll
        for (int i = 0; i < 4; i++) {
            int r = lr + 32 * i;
            uint32_t sw = r * 128 + ((lc ^ (r & 7)) << 4);
            cp_async16(ab + sw, gA + (size_t)(m0 + r) * (DDIM * 2) + kof + lc * 16);
            cp_async16(bb + sw, gB + (size_t)(n0 + r) * (DDIM * 2) + kof + lc * 16);
        }
        cp_commit();
    };

    load_stage(0);
    load_stage(1);

    // per-thread ldmatrix row indices (lane-dependent, stage-independent)
    uint32_t rA[2], rB[4];
    #pragma unroll
    for (int mt = 0; mt < 2; mt++)
        rA[mt] = wm * 32 + mt * 16 + (lane & 7) + ((lane >> 3) & 1) * 8;
    #pragma unroll
    for (int g = 0; g < 4; g++)
        rB[g] = wn * 64 + g * 16 + (lane & 7) + (lane >> 4) * 8;
    const uint32_t cAo = (lane >> 4);        // A: +chunk for k8..15 half
    const uint32_t cBo = ((lane >> 3) & 1);  // B: +chunk for k8..15 half

    float acc[2][8][4];
    #pragma unroll
    for (int mt = 0; mt < 2; mt++)
        #pragma unroll
        for (int nt = 0; nt < 8; nt++)
            #pragma unroll
            for (int q = 0; q < 4; q++) acc[mt][nt][q] = 0.0f;

    for (int s = 0; s < NK; s++) {
        if (s < NK - 2) cp_wait<1>(); else cp_wait<0>();
        __syncthreads();
        if (s + 2 < NK) load_stage(s + 2);

        const uint32_t ab = base + (s % STAGES) * STAGE_BYTES;
        const uint32_t bb = ab + A_BYTES;
        #pragma unroll
        for (int ks = 0; ks < 4; ks++) {               // 4 x k16 within BK=64
            uint32_t Af[2][4], Bf[4][4];
            #pragma unroll
            for (int mt = 0; mt < 2; mt++) {
                uint32_t c = ks * 2 + cAo;
                ldsm4(Af[mt], ab + rA[mt] * 128 + ((c ^ (rA[mt] & 7)) << 4));
            }
            #pragma unroll
            for (int g = 0; g < 4; g++) {
                uint32_t c = ks * 2 + cBo;
                ldsm4(Bf[g], bb + rB[g] * 128 + ((c ^ (rB[g] & 7)) << 4));
            }
            #pragma unroll
            for (int mt = 0; mt < 2; mt++)
                #pragma unroll
                for (int nt = 0; nt < 8; nt++)
                    mma16816(acc[mt][nt], Af[mt], &Bf[nt >> 1][(nt & 1) * 2]);
        }
    }

    // ---- fused softplus epilogue on register accumulators ----
    const float scale = *scale_p;
    const float bias = *bias_p;
    float loss = 0.0f;
    const int rbase = (lane >> 2);
    const int cbase = (lane & 3) * 2;
    #pragma unroll
    for (int mt = 0; mt < 2; mt++) {
        int fl0 = sFl[wm * 32 + mt * 16 + 0 + rbase];
        int fl1 = sFl[wm * 32 + mt * 16 + 8 + rbase];
        #pragma unroll
        for (int nt = 0; nt < 8; nt++) {
            int sl0 = sSl[wn * 64 + nt * 8 + cbase + 0];
            int sl1 = sSl[wn * 64 + nt * 8 + cbase + 1];
            #pragma unroll
            for (int q = 0; q < 4; q++) {
                int fl = (q >> 1) ? fl1 : fl0;
                int sl = (q & 1) ? sl1 : sl0;
                float z = fmaf(scale, acc[mt][nt][q], bias);
                float x = (fl == sl) ? -z : z;         // x = -label*z
                // softplus(x) = max(x,0) + log1p(exp(-|x|)),  |x| == |z|
                loss += fmaxf(x, 0.0f) + __logf(1.0f + __expf(-fabsf(z)));
            }
        }
    }

    // fixed-order reduction -> deterministic
    #pragma unroll
    for (int o = 16; o; o >>= 1) loss += __shfl_xor_sync(0xFFFFFFFFu, loss, o);
    __syncthreads();
    if (lane == 0) red[wid] = loss;
    __syncthreads();
    if (tid == 0) {
        double s = 0.0;
        #pragma unroll
        for (int i = 0; i < 8; i++) s += (double)red[i];
        g_partials[blockIdx.y * GRID_X + blockIdx.x] = s;
    }
}

// ---------------- k2: final deterministic reduce ----------------
__global__ void reduce_kernel(float* __restrict__ out) {
    __shared__ double sh[256];
    double s = 0.0;
    for (int i = threadIdx.x; i < NPART; i += 256) s += g_partials[i];
    sh[threadIdx.x] = s;
    __syncthreads();
    for (int o = 128; o; o >>= 1) {
        if (threadIdx.x < o) sh[threadIdx.x] += sh[threadIdx.x + o];
        __syncthreads();
    }
    if (threadIdx.x == 0) out[0] = (float)(sh[0] / (double)NTOK);
}

// ---------------- launch ----------------
extern "C" void kernel_launch(void* const* d_in, const int* in_sizes, int n_in,
                              void* d_out, int out_size) {
    const float* A  = (const float*)d_in[0];   // first_features
    const float* B  = (const float*)d_in[1];   // second_features
    const int*   fl = (const int*)d_in[2];     // first_label
    const int*   sl = (const int*)d_in[3];     // second_label
    const float* sc = (const float*)d_in[4];   // logit_scale
    const float* bi = (const float*)d_in[5];   // logit_bias

    cudaFuncSetAttribute(gemm_loss_kernel,
                         cudaFuncAttributeMaxDynamicSharedMemorySize, SMEM_TOTAL);

    const int n4_total = 2 * (NTOK * DDIM / 4);
    convert_kernel<<<(n4_total + 255) / 256, 256>>>(A, B);

    dim3 grid(GRID_X, GRID_Y);
    gemm_loss_kernel<<<grid, 256, SMEM_TOTAL>>>(fl, sl, sc, bi);

    reduce_kernel<<<1, 256>>>((float*)d_out);
}